// round 1
// baseline (speedup 1.0000x reference)
#include <cuda_runtime.h>
#include <cuda_bf16.h>
#include <cstdint>

// Problem constants (fixed shapes per metadata)
#define NMAX   50176
#define EMAX   1048576
#define INF    128
#define HEADS  3
#define HID    64
#define OUTC   64
#define D1     (HEADS*HID)   // 192

// ---------------- static scratch (no runtime allocation) ----------------
__device__ float g_h1 [(size_t)NMAX * D1];    // x @ W1
__device__ float g_h1p[(size_t)NMAX * D1];    // after agg + bias + ELU
__device__ float g_h2 [(size_t)NMAX * OUTC];  // h1p @ W2
__device__ float g_as1[(size_t)NMAX * HEADS];
__device__ float g_ad1[(size_t)NMAX * HEADS];
__device__ float g_as2[NMAX];
__device__ float g_ad2[NMAX];
__device__ int   g_cnt [NMAX];
__device__ int   g_fill[NMAX];
__device__ int   g_off [NMAX + 1];
__device__ int   g_csr [EMAX];

// ---------------- CSR build ----------------
__global__ void zero_kernel(int* a, int* b, int n) {
    int i = blockIdx.x * blockDim.x + threadIdx.x;
    if (i < n) { a[i] = 0; b[i] = 0; }
}

__global__ void hist_kernel(const int* __restrict__ dst, int* __restrict__ cnt, int E) {
    int i = blockIdx.x * blockDim.x + threadIdx.x;
    if (i < E) atomicAdd(&cnt[dst[i]], 1);
}

__global__ void scan_kernel(const int* __restrict__ cnt, int* __restrict__ off, int N) {
    __shared__ int sh[1024];
    int t = threadIdx.x;
    int per = (N + 1023) >> 10;
    int b = t * per;
    int e = min(b + per, N);
    int s = 0;
    for (int i = b; i < e; i++) s += cnt[i];
    sh[t] = s;
    __syncthreads();
    for (int o = 1; o < 1024; o <<= 1) {
        int v = (t >= o) ? sh[t - o] : 0;
        __syncthreads();
        sh[t] += v;
        __syncthreads();
    }
    int run = sh[t] - s;   // exclusive base
    for (int i = b; i < e; i++) { off[i] = run; run += cnt[i]; }
    if (t == 1023) off[N] = sh[1023];
}

__global__ void scatter_kernel(const int* __restrict__ src, const int* __restrict__ dst,
                               const int* __restrict__ off, int* __restrict__ fill,
                               int* __restrict__ csr, int E) {
    int i = blockIdx.x * blockDim.x + threadIdx.x;
    if (i < E) {
        int d = dst[i];
        int p = atomicAdd(&fill[d], 1);
        csr[off[d] + p] = src[i];
    }
}

// ---------------- fp32 tiled GEMM: C[M,N] = A[M,K] * B[K,N] ----------------
// BM=BN=64, BK=16, 256 threads, 4x4 microtile.
__global__ void __launch_bounds__(256) sgemm64(const float* __restrict__ A,
                                               const float* __restrict__ B,
                                               float* __restrict__ C,
                                               int M, int N, int K) {
    __shared__ float As[16][68];
    __shared__ float Bs[16][64];
    int bm = blockIdx.y * 64, bn = blockIdx.x * 64;
    int tid  = threadIdx.x;
    int tm   = tid >> 4, tn = tid & 15;
    int arow = tid >> 2, acol = (tid & 3) << 2;
    int brow = tid >> 4, bcol = (tid & 15) << 2;
    float acc[4][4] = {};
    for (int k0 = 0; k0 < K; k0 += 16) {
        float4 av = make_float4(0.f, 0.f, 0.f, 0.f);
        if (bm + arow < M)
            av = *(const float4*)(A + (size_t)(bm + arow) * K + k0 + acol);
        As[acol + 0][arow] = av.x;
        As[acol + 1][arow] = av.y;
        As[acol + 2][arow] = av.z;
        As[acol + 3][arow] = av.w;
        *(float4*)&Bs[brow][bcol] = *(const float4*)(B + (size_t)(k0 + brow) * N + bn + bcol);
        __syncthreads();
#pragma unroll
        for (int k = 0; k < 16; k++) {
            float4 a = *(float4*)&As[k][tm << 2];
            float4 b = *(float4*)&Bs[k][tn << 2];
            acc[0][0] = fmaf(a.x, b.x, acc[0][0]); acc[0][1] = fmaf(a.x, b.y, acc[0][1]);
            acc[0][2] = fmaf(a.x, b.z, acc[0][2]); acc[0][3] = fmaf(a.x, b.w, acc[0][3]);
            acc[1][0] = fmaf(a.y, b.x, acc[1][0]); acc[1][1] = fmaf(a.y, b.y, acc[1][1]);
            acc[1][2] = fmaf(a.y, b.z, acc[1][2]); acc[1][3] = fmaf(a.y, b.w, acc[1][3]);
            acc[2][0] = fmaf(a.z, b.x, acc[2][0]); acc[2][1] = fmaf(a.z, b.y, acc[2][1]);
            acc[2][2] = fmaf(a.z, b.z, acc[2][2]); acc[2][3] = fmaf(a.z, b.w, acc[2][3]);
            acc[3][0] = fmaf(a.w, b.x, acc[3][0]); acc[3][1] = fmaf(a.w, b.y, acc[3][1]);
            acc[3][2] = fmaf(a.w, b.z, acc[3][2]); acc[3][3] = fmaf(a.w, b.w, acc[3][3]);
        }
        __syncthreads();
    }
#pragma unroll
    for (int i = 0; i < 4; i++) {
        int r = bm + (tm << 2) + i;
        if (r < M) {
            float4 v = make_float4(acc[i][0], acc[i][1], acc[i][2], acc[i][3]);
            *(float4*)(C + (size_t)r * N + bn + (tn << 2)) = v;
        }
    }
}

// ---------------- per-node attention logits: as[n,h], ad[n,h] ----------------
__global__ void att_kernel(const float* __restrict__ h,
                           const float* __restrict__ ws, const float* __restrict__ wd,
                           float* __restrict__ as_o, float* __restrict__ ad_o,
                           int N, int H) {
    int gw   = (blockIdx.x * blockDim.x + threadIdx.x) >> 5;
    int lane = threadIdx.x & 31;
    if (gw >= N) return;
    const float* row = h + (size_t)gw * H * 64;
    for (int hd = 0; hd < H; hd++) {
        float s = 0.f, d = 0.f;
#pragma unroll
        for (int c = lane; c < 64; c += 32) {
            float v = row[hd * 64 + c];
            s = fmaf(v, ws[hd * 64 + c], s);
            d = fmaf(v, wd[hd * 64 + c], d);
        }
#pragma unroll
        for (int o = 16; o; o >>= 1) {
            s += __shfl_xor_sync(~0u, s, o);
            d += __shfl_xor_sync(~0u, d, o);
        }
        if (lane == 0) { as_o[(size_t)gw * H + hd] = s; ad_o[(size_t)gw * H + hd] = d; }
    }
}

// ---------------- per-destination online-softmax aggregation ----------------
// One block per node; blockDim = H*64; thread owns (head=tid>>6, ch=tid&63).
template <int H, bool ACT>
__global__ void __launch_bounds__(H * 64) agg_kernel(const float* __restrict__ h,
                                                     const float* __restrict__ as,
                                                     const float* __restrict__ ad,
                                                     const int* __restrict__ csr,
                                                     const int* __restrict__ off,
                                                     const float* __restrict__ bias,
                                                     float* __restrict__ out) {
    constexpr int D = H * 64;
    constexpr int CH = 32;
    int i    = blockIdx.x;
    int tid  = threadIdx.x;
    int head = tid >> 6;
    __shared__ int   s_src[CH];
    __shared__ float s_e[CH][H];
    __shared__ float s_ad[H];
    if (tid < H) s_ad[tid] = ad[(size_t)i * H + tid];
    __syncthreads();

    // self-loop initializes the running softmax
    float es = as[(size_t)i * H + head] + s_ad[head];
    es = es > 0.f ? es : 0.2f * es;
    float m   = es;
    float den = 1.0f;
    float acc = h[(size_t)i * D + tid];

    int b0 = off[i], b1 = off[i + 1];
    for (int base = b0; base < b1; base += CH) {
        int n = min(CH, b1 - base);
        __syncthreads();
        if (tid < n) {
            int s = csr[base + tid];
            s_src[tid] = s;
#pragma unroll
            for (int hh = 0; hh < H; hh++) {
                float e = as[(size_t)s * H + hh] + s_ad[hh];
                s_e[tid][hh] = e > 0.f ? e : 0.2f * e;
            }
        }
        __syncthreads();
        float nm = m;
        for (int j = 0; j < n; j++) nm = fmaxf(nm, s_e[j][head]);
        if (nm > m) {
            float sc = __expf(m - nm);
            den *= sc; acc *= sc; m = nm;
        }
        for (int j = 0; j < n; j++) {
            float w = __expf(s_e[j][head] - m);
            den += w;
            acc = fmaf(w, h[(size_t)s_src[j] * D + tid], acc);
        }
    }
    float r = acc / (den + 1e-16f) + bias[tid];
    if (ACT) r = r > 0.f ? r : expm1f(r);
    out[(size_t)i * D + tid] = r;
}

// ---------------- launch ----------------
extern "C" void kernel_launch(void* const* d_in, const int* in_sizes, int n_in,
                              void* d_out, int out_size) {
    const float* x   = (const float*)d_in[0];
    const int*   ei  = (const int*)  d_in[1];
    const float* W1  = (const float*)d_in[2];
    const float* as1 = (const float*)d_in[3];
    const float* ad1 = (const float*)d_in[4];
    const float* b1  = (const float*)d_in[5];
    const float* W2  = (const float*)d_in[6];
    const float* as2 = (const float*)d_in[7];
    const float* ad2 = (const float*)d_in[8];
    const float* b2  = (const float*)d_in[9];
    float* out = (float*)d_out;

    int N = in_sizes[0] / INF;
    int E = in_sizes[1] / 2;
    const int* esrc = ei;
    const int* edst = ei + E;

    float *p_h1, *p_h1p, *p_h2, *p_as1, *p_ad1, *p_as2, *p_ad2;
    int *p_cnt, *p_fill, *p_off, *p_csr;
    cudaGetSymbolAddress((void**)&p_h1,  g_h1);
    cudaGetSymbolAddress((void**)&p_h1p, g_h1p);
    cudaGetSymbolAddress((void**)&p_h2,  g_h2);
    cudaGetSymbolAddress((void**)&p_as1, g_as1);
    cudaGetSymbolAddress((void**)&p_ad1, g_ad1);
    cudaGetSymbolAddress((void**)&p_as2, g_as2);
    cudaGetSymbolAddress((void**)&p_ad2, g_ad2);
    cudaGetSymbolAddress((void**)&p_cnt,  g_cnt);
    cudaGetSymbolAddress((void**)&p_fill, g_fill);
    cudaGetSymbolAddress((void**)&p_off,  g_off);
    cudaGetSymbolAddress((void**)&p_csr,  g_csr);

    // CSR build (by destination)
    zero_kernel<<<(N + 255) / 256, 256>>>(p_cnt, p_fill, N);
    hist_kernel<<<(E + 255) / 256, 256>>>(edst, p_cnt, E);
    scan_kernel<<<1, 1024>>>(p_cnt, p_off, N);
    scatter_kernel<<<(E + 255) / 256, 256>>>(esrc, edst, p_off, p_fill, p_csr, E);

    // Layer 1
    {
        dim3 g(D1 / 64, (N + 63) / 64);
        sgemm64<<<g, 256>>>(x, W1, p_h1, N, D1, INF);
    }
    att_kernel<<<(N + 7) / 8, 256>>>(p_h1, as1, ad1, p_as1, p_ad1, N, HEADS);
    agg_kernel<HEADS, true><<<N, D1>>>(p_h1, p_as1, p_ad1, p_csr, p_off, b1, p_h1p);

    // Layer 2
    {
        dim3 g(OUTC / 64, (N + 63) / 64);
        sgemm64<<<g, 256>>>(p_h1p, W2, p_h2, N, OUTC, D1);
    }
    att_kernel<<<(N + 7) / 8, 256>>>(p_h2, as2, ad2, p_as2, p_ad2, N, 1);
    agg_kernel<1, false><<<N, OUTC>>>(p_h2, p_as2, p_ad2, p_csr, p_off, b2, out);
}

// round 2
// speedup vs baseline: 1.0265x; 1.0265x over previous
#include <cuda_runtime.h>
#include <cuda_bf16.h>
#include <cstdint>

// Problem constants (fixed shapes per metadata)
#define NMAX   50176
#define EMAX   1048576
#define INF    128
#define HEADS  3
#define HID    64
#define OUTC   64
#define D1     (HEADS*HID)   // 192

// ---------------- static scratch (no runtime allocation) ----------------
__device__ float g_h1 [(size_t)NMAX * D1];    // x @ W1
__device__ float g_h1p[(size_t)NMAX * D1];    // after agg + bias + ELU
__device__ float g_h2 [(size_t)NMAX * OUTC];  // h1p @ W2
__device__ float g_as1[(size_t)NMAX * HEADS];
__device__ float g_ad1[(size_t)NMAX * HEADS];
__device__ float g_as2[NMAX];
__device__ float g_ad2[NMAX];
__device__ int   g_cnt [NMAX];
__device__ int   g_fill[NMAX];
__device__ int   g_off [NMAX + 1];
__device__ int   g_csr [EMAX];

// ---------------- CSR build ----------------
__global__ void zero_kernel(int* a, int* b, int n) {
    int i = blockIdx.x * blockDim.x + threadIdx.x;
    if (i < n) { a[i] = 0; b[i] = 0; }
}

__global__ void hist_kernel(const int* __restrict__ dst, int* __restrict__ cnt, int E) {
    int i = blockIdx.x * blockDim.x + threadIdx.x;
    if (i < E) atomicAdd(&cnt[dst[i]], 1);
}

__global__ void scan_kernel(const int* __restrict__ cnt, int* __restrict__ off, int N) {
    __shared__ int sh[1024];
    int t = threadIdx.x;
    int per = (N + 1023) >> 10;
    int b = t * per;
    int e = min(b + per, N);
    int s = 0;
    for (int i = b; i < e; i++) s += cnt[i];
    sh[t] = s;
    __syncthreads();
    for (int o = 1; o < 1024; o <<= 1) {
        int v = (t >= o) ? sh[t - o] : 0;
        __syncthreads();
        sh[t] += v;
        __syncthreads();
    }
    int run = sh[t] - s;   // exclusive base
    for (int i = b; i < e; i++) { off[i] = run; run += cnt[i]; }
    if (t == 1023) off[N] = sh[1023];
}

__global__ void scatter_kernel(const int* __restrict__ src, const int* __restrict__ dst,
                               const int* __restrict__ off, int* __restrict__ fill,
                               int* __restrict__ csr, int E) {
    int i = blockIdx.x * blockDim.x + threadIdx.x;
    if (i < E) {
        int d = dst[i];
        int p = atomicAdd(&fill[d], 1);
        csr[off[d] + p] = src[i];
    }
}

// ---------------- fp32 GEMM: C[M,N] = A[M,K] * B[K,N] ----------------
// BM=256, BN=64, BK=16. 256 threads, 8x8 microtile (thread grid 32x8).
// A staged via regs->STS (transposed to As[k][m]); B staged via cp.async.
// Double-buffered smem; conflict-free broadcast LDS.128 fragment loads.
#define BM 256
#define BN 64
#define BK 16

__device__ __forceinline__ void cp_async16(void* smem_dst, const void* gmem_src) {
    uint32_t s = (uint32_t)__cvta_generic_to_shared(smem_dst);
    asm volatile("cp.async.ca.shared.global [%0], [%1], 16;\n" :: "r"(s), "l"(gmem_src));
}

__global__ void __launch_bounds__(256, 2) gemm_big(const float* __restrict__ A,
                                                   const float* __restrict__ B,
                                                   float* __restrict__ C,
                                                   int M, int N, int K) {
    __shared__ float As[2][BK][BM];   // 32 KB
    __shared__ float Bs[2][BK][BN];   // 8 KB
    int bm = blockIdx.y * BM, bn = blockIdx.x * BN;
    int tid = threadIdx.x;
    int tm = tid >> 3;          // 0..31  (8 rows each)
    int tn = tid & 7;           // 0..7   (8 cols each)

    // A load: thread owns one row, 16 consecutive k (4x float4)
    int arow = bm + tid;
    bool aval = arow < M;
    const float* aptr = aval ? (A + (size_t)arow * K) : A;   // safe base
    // B load: one float4 per thread
    int brow = tid >> 4;               // 0..15
    int bcol = (tid & 15) << 2;        // 0,4,...,60

    float acc[8][8];
#pragma unroll
    for (int i = 0; i < 8; i++)
#pragma unroll
        for (int j = 0; j < 8; j++) acc[i][j] = 0.f;

    float4 areg[4];
    const float4 fz = make_float4(0.f, 0.f, 0.f, 0.f);

    // ---- prologue: stage 0 ----
#pragma unroll
    for (int i = 0; i < 4; i++)
        areg[i] = aval ? *(const float4*)(aptr + i * 4) : fz;
    cp_async16(&Bs[0][brow][bcol], B + (size_t)brow * N + bn + bcol);
    asm volatile("cp.async.commit_group;\n");
#pragma unroll
    for (int i = 0; i < 4; i++) {
        As[0][i * 4 + 0][tid] = areg[i].x;
        As[0][i * 4 + 1][tid] = areg[i].y;
        As[0][i * 4 + 2][tid] = areg[i].z;
        As[0][i * 4 + 3][tid] = areg[i].w;
    }
    asm volatile("cp.async.wait_group 0;\n");
    __syncthreads();

    int niter = K / BK;
    for (int it = 0; it < niter; it++) {
        int cur = it & 1, nxt = cur ^ 1;
        bool more = (it + 1) < niter;
        if (more) {
            int k0 = (it + 1) * BK;
#pragma unroll
            for (int i = 0; i < 4; i++)
                areg[i] = aval ? *(const float4*)(aptr + k0 + i * 4) : fz;
            cp_async16(&Bs[nxt][brow][bcol], B + (size_t)(k0 + brow) * N + bn + bcol);
            asm volatile("cp.async.commit_group;\n");
        }
#pragma unroll
        for (int k = 0; k < BK; k++) {
            float4 a0 = *(float4*)&As[cur][k][tm * 8];
            float4 a1 = *(float4*)&As[cur][k][tm * 8 + 4];
            float4 b0 = *(float4*)&Bs[cur][k][tn * 8];
            float4 b1 = *(float4*)&Bs[cur][k][tn * 8 + 4];
            float av[8] = {a0.x, a0.y, a0.z, a0.w, a1.x, a1.y, a1.z, a1.w};
            float bv[8] = {b0.x, b0.y, b0.z, b0.w, b1.x, b1.y, b1.z, b1.w};
#pragma unroll
            for (int i = 0; i < 8; i++)
#pragma unroll
                for (int j = 0; j < 8; j++)
                    acc[i][j] = fmaf(av[i], bv[j], acc[i][j]);
        }
        if (more) {
#pragma unroll
            for (int i = 0; i < 4; i++) {
                As[nxt][i * 4 + 0][tid] = areg[i].x;
                As[nxt][i * 4 + 1][tid] = areg[i].y;
                As[nxt][i * 4 + 2][tid] = areg[i].z;
                As[nxt][i * 4 + 3][tid] = areg[i].w;
            }
            asm volatile("cp.async.wait_group 0;\n");
            __syncthreads();
        }
    }

    // ---- epilogue ----
#pragma unroll
    for (int i = 0; i < 8; i++) {
        int r = bm + tm * 8 + i;
        if (r < M) {
            float* cp = C + (size_t)r * N + bn + tn * 8;
            *(float4*)(cp)     = make_float4(acc[i][0], acc[i][1], acc[i][2], acc[i][3]);
            *(float4*)(cp + 4) = make_float4(acc[i][4], acc[i][5], acc[i][6], acc[i][7]);
        }
    }
}

// ---------------- per-node attention logits: as[n,h], ad[n,h] ----------------
__global__ void att_kernel(const float* __restrict__ h,
                           const float* __restrict__ ws, const float* __restrict__ wd,
                           float* __restrict__ as_o, float* __restrict__ ad_o,
                           int N, int H) {
    int gw   = (blockIdx.x * blockDim.x + threadIdx.x) >> 5;
    int lane = threadIdx.x & 31;
    if (gw >= N) return;
    const float* row = h + (size_t)gw * H * 64;
    for (int hd = 0; hd < H; hd++) {
        float s = 0.f, d = 0.f;
#pragma unroll
        for (int c = lane; c < 64; c += 32) {
            float v = row[hd * 64 + c];
            s = fmaf(v, ws[hd * 64 + c], s);
            d = fmaf(v, wd[hd * 64 + c], d);
        }
#pragma unroll
        for (int o = 16; o; o >>= 1) {
            s += __shfl_xor_sync(~0u, s, o);
            d += __shfl_xor_sync(~0u, d, o);
        }
        if (lane == 0) { as_o[(size_t)gw * H + hd] = s; ad_o[(size_t)gw * H + hd] = d; }
    }
}

// ---------------- per-destination online-softmax aggregation ----------------
// One block per node; blockDim = H*64; thread owns (head=tid>>6, ch=tid&63).
template <int H, bool ACT>
__global__ void __launch_bounds__(H * 64) agg_kernel(const float* __restrict__ h,
                                                     const float* __restrict__ as,
                                                     const float* __restrict__ ad,
                                                     const int* __restrict__ csr,
                                                     const int* __restrict__ off,
                                                     const float* __restrict__ bias,
                                                     float* __restrict__ out) {
    constexpr int D = H * 64;
    constexpr int CH = 32;
    int i    = blockIdx.x;
    int tid  = threadIdx.x;
    int head = tid >> 6;
    __shared__ int   s_src[CH];
    __shared__ float s_e[CH][H];
    __shared__ float s_ad[H];
    if (tid < H) s_ad[tid] = ad[(size_t)i * H + tid];
    __syncthreads();

    // self-loop initializes the running softmax
    float es = as[(size_t)i * H + head] + s_ad[head];
    es = es > 0.f ? es : 0.2f * es;
    float m   = es;
    float den = 1.0f;
    float acc = h[(size_t)i * D + tid];

    int b0 = off[i], b1 = off[i + 1];
    for (int base = b0; base < b1; base += CH) {
        int n = min(CH, b1 - base);
        __syncthreads();
        if (tid < n) {
            int s = csr[base + tid];
            s_src[tid] = s;
#pragma unroll
            for (int hh = 0; hh < H; hh++) {
                float e = as[(size_t)s * H + hh] + s_ad[hh];
                s_e[tid][hh] = e > 0.f ? e : 0.2f * e;
            }
        }
        __syncthreads();
        float nm = m;
#pragma unroll 4
        for (int j = 0; j < n; j++) nm = fmaxf(nm, s_e[j][head]);
        if (nm > m) {
            float sc = __expf(m - nm);
            den *= sc; acc *= sc; m = nm;
        }
#pragma unroll 4
        for (int j = 0; j < n; j++) {
            float w = __expf(s_e[j][head] - m);
            den += w;
            acc = fmaf(w, h[(size_t)s_src[j] * D + tid], acc);
        }
    }
    float r = acc / (den + 1e-16f) + bias[tid];
    if (ACT) r = r > 0.f ? r : expm1f(r);
    out[(size_t)i * D + tid] = r;
}

// ---------------- launch ----------------
extern "C" void kernel_launch(void* const* d_in, const int* in_sizes, int n_in,
                              void* d_out, int out_size) {
    const float* x   = (const float*)d_in[0];
    const int*   ei  = (const int*)  d_in[1];
    const float* W1  = (const float*)d_in[2];
    const float* as1 = (const float*)d_in[3];
    const float* ad1 = (const float*)d_in[4];
    const float* b1  = (const float*)d_in[5];
    const float* W2  = (const float*)d_in[6];
    const float* as2 = (const float*)d_in[7];
    const float* ad2 = (const float*)d_in[8];
    const float* b2  = (const float*)d_in[9];
    float* out = (float*)d_out;

    int N = in_sizes[0] / INF;
    int E = in_sizes[1] / 2;
    const int* esrc = ei;
    const int* edst = ei + E;

    float *p_h1, *p_h1p, *p_h2, *p_as1, *p_ad1, *p_as2, *p_ad2;
    int *p_cnt, *p_fill, *p_off, *p_csr;
    cudaGetSymbolAddress((void**)&p_h1,  g_h1);
    cudaGetSymbolAddress((void**)&p_h1p, g_h1p);
    cudaGetSymbolAddress((void**)&p_h2,  g_h2);
    cudaGetSymbolAddress((void**)&p_as1, g_as1);
    cudaGetSymbolAddress((void**)&p_ad1, g_ad1);
    cudaGetSymbolAddress((void**)&p_as2, g_as2);
    cudaGetSymbolAddress((void**)&p_ad2, g_ad2);
    cudaGetSymbolAddress((void**)&p_cnt,  g_cnt);
    cudaGetSymbolAddress((void**)&p_fill, g_fill);
    cudaGetSymbolAddress((void**)&p_off,  g_off);
    cudaGetSymbolAddress((void**)&p_csr,  g_csr);

    // Side stream + events, created once on the (uncaptured) correctness call.
    static cudaStream_t s_side = nullptr;
    static cudaEvent_t  ev_fork = nullptr, ev_join = nullptr;
    if (s_side == nullptr) {
        cudaStreamCreateWithFlags(&s_side, cudaStreamNonBlocking);
        cudaEventCreateWithFlags(&ev_fork, cudaEventDisableTiming);
        cudaEventCreateWithFlags(&ev_join, cudaEventDisableTiming);
    }

    bool forked = (s_side != nullptr && ev_fork != nullptr && ev_join != nullptr);
    cudaStream_t sc = forked ? s_side : (cudaStream_t)0;  // CSR stream

    if (forked) {
        cudaEventRecord(ev_fork, 0);
        cudaStreamWaitEvent(s_side, ev_fork, 0);
    }
    // CSR build (by destination) — overlapped with layer-1 GEMM
    zero_kernel<<<(N + 255) / 256, 256, 0, sc>>>(p_cnt, p_fill, N);
    hist_kernel<<<(E + 255) / 256, 256, 0, sc>>>(edst, p_cnt, E);
    scan_kernel<<<1, 1024, 0, sc>>>(p_cnt, p_off, N);
    scatter_kernel<<<(E + 255) / 256, 256, 0, sc>>>(esrc, edst, p_off, p_fill, p_csr, E);
    if (forked) cudaEventRecord(ev_join, s_side);

    // Layer 1
    {
        dim3 g(D1 / BN, (N + BM - 1) / BM);
        gemm_big<<<g, 256>>>(x, W1, p_h1, N, D1, INF);
    }
    att_kernel<<<(N + 7) / 8, 256>>>(p_h1, as1, ad1, p_as1, p_ad1, N, HEADS);
    if (forked) cudaStreamWaitEvent(0, ev_join, 0);
    agg_kernel<HEADS, true><<<N, D1>>>(p_h1, p_as1, p_ad1, p_csr, p_off, b1, p_h1p);

    // Layer 2
    {
        dim3 g(OUTC / BN, (N + BM - 1) / BM);
        gemm_big<<<g, 256>>>(p_h1p, W2, p_h2, N, OUTC, D1);
    }
    att_kernel<<<(N + 7) / 8, 256>>>(p_h2, as2, ad2, p_as2, p_ad2, N, 1);
    agg_kernel<1, false><<<N, OUTC>>>(p_h2, p_as2, p_ad2, p_csr, p_off, b2, out);
}

// round 3
// speedup vs baseline: 1.2479x; 1.2158x over previous
#include <cuda_runtime.h>
#include <cuda_bf16.h>
#include <cstdint>

// Problem constants (fixed shapes per metadata)
#define NMAX   50176
#define EMAX   1048576
#define INF    128
#define HEADS  3
#define HID    64
#define OUTC   64
#define D1     (HEADS*HID)   // 192

// ---------------- static scratch (no runtime allocation) ----------------
__device__ float g_h1 [(size_t)NMAX * D1];
__device__ float g_h1p[(size_t)NMAX * D1];
__device__ float g_h2 [(size_t)NMAX * OUTC];
__device__ float g_as1[(size_t)NMAX * HEADS];
__device__ float g_ad1[(size_t)NMAX * HEADS];
__device__ float g_as2[NMAX];
__device__ float g_ad2[NMAX];
__device__ int   g_cnt [NMAX];
__device__ int   g_fill[NMAX];
__device__ int   g_off [NMAX + 1];
__device__ int   g_csr [EMAX];

// ---------------- CSR build ----------------
__global__ void zero_kernel(int* a, int* b, int n) {
    int i = blockIdx.x * blockDim.x + threadIdx.x;
    if (i < n) { a[i] = 0; b[i] = 0; }
}

__global__ void hist_kernel(const int* __restrict__ dst, int* __restrict__ cnt, int E) {
    int i = blockIdx.x * blockDim.x + threadIdx.x;
    if (i < E) atomicAdd(&cnt[dst[i]], 1);
}

__global__ void scan_kernel(const int* __restrict__ cnt, int* __restrict__ off, int N) {
    __shared__ int sh[1024];
    int t = threadIdx.x;
    int per = (N + 1023) >> 10;
    int b = t * per;
    int e = min(b + per, N);
    int s = 0;
    for (int i = b; i < e; i++) s += cnt[i];
    sh[t] = s;
    __syncthreads();
    for (int o = 1; o < 1024; o <<= 1) {
        int v = (t >= o) ? sh[t - o] : 0;
        __syncthreads();
        sh[t] += v;
        __syncthreads();
    }
    int run = sh[t] - s;
    for (int i = b; i < e; i++) { off[i] = run; run += cnt[i]; }
    if (t == 1023) off[N] = sh[1023];
}

__global__ void scatter_kernel(const int* __restrict__ src, const int* __restrict__ dst,
                               const int* __restrict__ off, int* __restrict__ fill,
                               int* __restrict__ csr, int E) {
    int i = blockIdx.x * blockDim.x + threadIdx.x;
    if (i < E) {
        int d = dst[i];
        int p = atomicAdd(&fill[d], 1);
        csr[off[d] + p] = src[i];
    }
}

// ---------------- tf32 tensor-core GEMM: C[M,N] = A[M,K] * B[K,N] ----------------
// BM=128, BN=64, BK=32. 256 threads = 8 warps in 4x2 grid; warp tile 32x32.
// mma.sync.m16n8k8 tf32, fp32 accumulate. Single-buffered smem (K loop is short;
// inter-block overlap at 3 blocks/SM hides the sync gaps).
#define GBM 128
#define GBN 64
#define GBK 32
#define AS_STRIDE (GBK + 4)   // 36 words: frag loads land on distinct banks (4r+c)
#define BS_STRIDE 72          // 72 words: frag loads land on distinct banks (8c+n)

__device__ __forceinline__ uint32_t f2tf32(float f) {
    uint32_t r;
    asm volatile("cvt.rna.tf32.f32 %0, %1;\n" : "=r"(r) : "f"(f));
    return r;
}

__device__ __forceinline__ void mma_tf32(float* d, const uint32_t* a, const uint32_t* b) {
    asm volatile(
        "mma.sync.aligned.m16n8k8.row.col.f32.tf32.tf32.f32 "
        "{%0,%1,%2,%3}, {%4,%5,%6,%7}, {%8,%9}, {%0,%1,%2,%3};\n"
        : "+f"(d[0]), "+f"(d[1]), "+f"(d[2]), "+f"(d[3])
        : "r"(a[0]), "r"(a[1]), "r"(a[2]), "r"(a[3]), "r"(b[0]), "r"(b[1]));
}

__global__ void __launch_bounds__(256) gemm_tc(const float* __restrict__ A,
                                               const float* __restrict__ B,
                                               float* __restrict__ C,
                                               int M, int N, int K) {
    __shared__ uint32_t As[GBM][AS_STRIDE];   // 18 KB
    __shared__ uint32_t Bs[GBK][BS_STRIDE];   // 9 KB
    int bm = blockIdx.y * GBM, bn = blockIdx.x * GBN;
    int tid  = threadIdx.x;
    int lane = tid & 31;
    int warp = tid >> 5;
    int wm = (warp >> 1) * 32;       // warp row base within block tile
    int wn = (warp & 1) * 32;        // warp col base

    // A loader: 4 rows per thread (row = tid>>3 + 32*i), 4 consecutive k
    int a_r   = tid >> 3;
    int a_kc  = (tid & 7) << 2;
    // B loader: 2 rows per thread, float4 of n
    int b_k   = tid >> 4;
    int b_n   = (tid & 15) << 2;

    float d[2][4][4];
#pragma unroll
    for (int i = 0; i < 2; i++)
#pragma unroll
        for (int j = 0; j < 4; j++)
#pragma unroll
            for (int l = 0; l < 4; l++) d[i][j][l] = 0.f;

    int g = lane >> 2;    // group id 0..7
    int tg = lane & 3;    // thread-in-group 0..3

    for (int k0 = 0; k0 < K; k0 += GBK) {
        // ---- stage A (cvt to tf32) ----
#pragma unroll
        for (int i = 0; i < 4; i++) {
            int row = a_r + i * 32;
            int grow = bm + row;
            grow = grow < M ? grow : M - 1;   // clamp: invalid rows only feed unstored outputs
            float4 v = *(const float4*)(A + (size_t)grow * K + k0 + a_kc);
            uint4 u;
            u.x = f2tf32(v.x); u.y = f2tf32(v.y); u.z = f2tf32(v.z); u.w = f2tf32(v.w);
            *(uint4*)&As[row][a_kc] = u;
        }
        // ---- stage B (cvt to tf32) ----
#pragma unroll
        for (int i = 0; i < 2; i++) {
            int kk = b_k + i * 16;
            float4 v = *(const float4*)(B + (size_t)(k0 + kk) * N + bn + b_n);
            uint4 u;
            u.x = f2tf32(v.x); u.y = f2tf32(v.y); u.z = f2tf32(v.z); u.w = f2tf32(v.w);
            *(uint4*)&Bs[kk][b_n] = u;
        }
        __syncthreads();

        // ---- compute: 4 k8 steps ----
#pragma unroll
        for (int kk = 0; kk < GBK; kk += 8) {
            uint32_t afrag[2][4];
#pragma unroll
            for (int mi = 0; mi < 2; mi++) {
                int r = wm + mi * 16 + g;
                afrag[mi][0] = As[r][kk + tg];
                afrag[mi][1] = As[r + 8][kk + tg];
                afrag[mi][2] = As[r][kk + tg + 4];
                afrag[mi][3] = As[r + 8][kk + tg + 4];
            }
#pragma unroll
            for (int ni = 0; ni < 4; ni++) {
                uint32_t bfrag[2];
                int n = wn + ni * 8 + g;
                bfrag[0] = Bs[kk + tg][n];
                bfrag[1] = Bs[kk + tg + 4][n];
                mma_tf32(d[0][ni], afrag[0], bfrag);
                mma_tf32(d[1][ni], afrag[1], bfrag);
            }
        }
        __syncthreads();
    }

    // ---- epilogue ----
#pragma unroll
    for (int mi = 0; mi < 2; mi++) {
#pragma unroll
        for (int ni = 0; ni < 4; ni++) {
            int r0 = bm + wm + mi * 16 + g;
            int c  = bn + wn + ni * 8 + tg * 2;
            if (r0 < M)
                *(float2*)(C + (size_t)r0 * N + c) = make_float2(d[mi][ni][0], d[mi][ni][1]);
            if (r0 + 8 < M)
                *(float2*)(C + (size_t)(r0 + 8) * N + c) = make_float2(d[mi][ni][2], d[mi][ni][3]);
        }
    }
}

// ---------------- per-node attention logits: as[n,h], ad[n,h] ----------------
__global__ void att_kernel(const float* __restrict__ h,
                           const float* __restrict__ ws, const float* __restrict__ wd,
                           float* __restrict__ as_o, float* __restrict__ ad_o,
                           int N, int H) {
    int gw   = (blockIdx.x * blockDim.x + threadIdx.x) >> 5;
    int lane = threadIdx.x & 31;
    if (gw >= N) return;
    const float* row = h + (size_t)gw * H * 64;
    for (int hd = 0; hd < H; hd++) {
        float s = 0.f, d = 0.f;
#pragma unroll
        for (int c = lane; c < 64; c += 32) {
            float v = row[hd * 64 + c];
            s = fmaf(v, ws[hd * 64 + c], s);
            d = fmaf(v, wd[hd * 64 + c], d);
        }
#pragma unroll
        for (int o = 16; o; o >>= 1) {
            s += __shfl_xor_sync(~0u, s, o);
            d += __shfl_xor_sync(~0u, d, o);
        }
        if (lane == 0) { as_o[(size_t)gw * H + hd] = s; ad_o[(size_t)gw * H + hd] = d; }
    }
}

// ---------------- per-destination online-softmax aggregation ----------------
// One block per node; blockDim = H*64; thread owns (head=tid>>6, ch=tid&63).
// Softmax weights are computed ONCE per chunk (CH*H exps, shared), not per-thread.
template <int H, bool ACT>
__global__ void __launch_bounds__(H * 64) agg_kernel(const float* __restrict__ h,
                                                     const float* __restrict__ as,
                                                     const float* __restrict__ ad,
                                                     const int* __restrict__ csr,
                                                     const int* __restrict__ off,
                                                     const float* __restrict__ bias,
                                                     float* __restrict__ out) {
    constexpr int D = H * 64;
    constexpr int CH = 32;
    int i    = blockIdx.x;
    int tid  = threadIdx.x;
    int head = tid >> 6;
    __shared__ int   s_src[CH];
    __shared__ float s_w[CH][H];   // logits, then exp-weights
    __shared__ float s_ad[H];
    __shared__ float s_m[H];
    if (tid < H) s_ad[tid] = ad[(size_t)i * H + tid];
    __syncthreads();

    // self-loop initializes the running softmax (same value across a head's 64 threads)
    float es = as[(size_t)i * H + head] + s_ad[head];
    es = es > 0.f ? es : 0.2f * es;
    float m   = es;
    float den = 1.0f;
    float acc = h[(size_t)i * D + tid];

    int b0 = off[i], b1 = off[i + 1];
    for (int base = b0; base < b1; base += CH) {
        int n = min(CH, b1 - base);
        __syncthreads();   // protect s_w reuse across chunks
        if (tid < n) {
            int s = csr[base + tid];
            s_src[tid] = s;
#pragma unroll
            for (int hh = 0; hh < H; hh++) {
                float e = as[(size_t)s * H + hh] + s_ad[hh];
                s_w[tid][hh] = e > 0.f ? e : 0.2f * e;
            }
        }
        __syncthreads();
        // running max update (identical across a head's threads)
        float nm = m;
        for (int j = 0; j < n; j++) nm = fmaxf(nm, s_w[j][head]);
        if (nm > m) {
            float sc = __expf(m - nm);
            den *= sc; acc *= sc; m = nm;
        }
        if ((tid & 63) == 0) s_m[head] = m;
        __syncthreads();
        // exponentiate once: CH*H values by the first CH*H threads
        if (tid < CH * H) {
            int j  = tid & (CH - 1);
            int hh = tid >> 5;
            if (j < n) s_w[j][hh] = __expf(s_w[j][hh] - s_m[hh]);
        }
        __syncthreads();
        // gather + weighted accumulate, manual 4-way load batching (MLP=4)
        int j = 0;
        for (; j + 4 <= n; j += 4) {
            int s0 = s_src[j], s1 = s_src[j + 1], s2 = s_src[j + 2], s3 = s_src[j + 3];
            float v0 = h[(size_t)s0 * D + tid];
            float v1 = h[(size_t)s1 * D + tid];
            float v2 = h[(size_t)s2 * D + tid];
            float v3 = h[(size_t)s3 * D + tid];
            float w0 = s_w[j][head], w1 = s_w[j + 1][head];
            float w2 = s_w[j + 2][head], w3 = s_w[j + 3][head];
            den += (w0 + w1) + (w2 + w3);
            acc = fmaf(w0, v0, acc);
            acc = fmaf(w1, v1, acc);
            acc = fmaf(w2, v2, acc);
            acc = fmaf(w3, v3, acc);
        }
        for (; j < n; j++) {
            float w = s_w[j][head];
            den += w;
            acc = fmaf(w, h[(size_t)s_src[j] * D + tid], acc);
        }
    }
    float r = acc / (den + 1e-16f) + bias[tid];
    if (ACT) r = r > 0.f ? r : expm1f(r);
    out[(size_t)i * D + tid] = r;
}

// ---------------- launch ----------------
extern "C" void kernel_launch(void* const* d_in, const int* in_sizes, int n_in,
                              void* d_out, int out_size) {
    const float* x   = (const float*)d_in[0];
    const int*   ei  = (const int*)  d_in[1];
    const float* W1  = (const float*)d_in[2];
    const float* as1 = (const float*)d_in[3];
    const float* ad1 = (const float*)d_in[4];
    const float* b1  = (const float*)d_in[5];
    const float* W2  = (const float*)d_in[6];
    const float* as2 = (const float*)d_in[7];
    const float* ad2 = (const float*)d_in[8];
    const float* b2  = (const float*)d_in[9];
    float* out = (float*)d_out;

    int N = in_sizes[0] / INF;
    int E = in_sizes[1] / 2;
    const int* esrc = ei;
    const int* edst = ei + E;

    float *p_h1, *p_h1p, *p_h2, *p_as1, *p_ad1, *p_as2, *p_ad2;
    int *p_cnt, *p_fill, *p_off, *p_csr;
    cudaGetSymbolAddress((void**)&p_h1,  g_h1);
    cudaGetSymbolAddress((void**)&p_h1p, g_h1p);
    cudaGetSymbolAddress((void**)&p_h2,  g_h2);
    cudaGetSymbolAddress((void**)&p_as1, g_as1);
    cudaGetSymbolAddress((void**)&p_ad1, g_ad1);
    cudaGetSymbolAddress((void**)&p_as2, g_as2);
    cudaGetSymbolAddress((void**)&p_ad2, g_ad2);
    cudaGetSymbolAddress((void**)&p_cnt,  g_cnt);
    cudaGetSymbolAddress((void**)&p_fill, g_fill);
    cudaGetSymbolAddress((void**)&p_off,  g_off);
    cudaGetSymbolAddress((void**)&p_csr,  g_csr);

    // Side stream + events (created once, on the uncaptured correctness call)
    static cudaStream_t s_side = nullptr;
    static cudaEvent_t  ev_fork = nullptr, ev_join = nullptr;
    if (s_side == nullptr) {
        cudaStreamCreateWithFlags(&s_side, cudaStreamNonBlocking);
        cudaEventCreateWithFlags(&ev_fork, cudaEventDisableTiming);
        cudaEventCreateWithFlags(&ev_join, cudaEventDisableTiming);
    }
    bool forked = (s_side != nullptr && ev_fork != nullptr && ev_join != nullptr);
    cudaStream_t sc = forked ? s_side : (cudaStream_t)0;

    if (forked) {
        cudaEventRecord(ev_fork, 0);
        cudaStreamWaitEvent(s_side, ev_fork, 0);
    }
    // CSR build (by destination) — overlapped with layer-1 GEMM
    zero_kernel<<<(N + 255) / 256, 256, 0, sc>>>(p_cnt, p_fill, N);
    hist_kernel<<<(E + 255) / 256, 256, 0, sc>>>(edst, p_cnt, E);
    scan_kernel<<<1, 1024, 0, sc>>>(p_cnt, p_off, N);
    scatter_kernel<<<(E + 255) / 256, 256, 0, sc>>>(esrc, edst, p_off, p_fill, p_csr, E);
    if (forked) cudaEventRecord(ev_join, s_side);

    // Layer 1
    {
        dim3 g(D1 / GBN, (N + GBM - 1) / GBM);
        gemm_tc<<<g, 256>>>(x, W1, p_h1, N, D1, INF);
    }
    att_kernel<<<(N + 7) / 8, 256>>>(p_h1, as1, ad1, p_as1, p_ad1, N, HEADS);
    if (forked) cudaStreamWaitEvent(0, ev_join, 0);
    agg_kernel<HEADS, true><<<N, D1>>>(p_h1, p_as1, p_ad1, p_csr, p_off, b1, p_h1p);

    // Layer 2
    {
        dim3 g(OUTC / GBN, (N + GBM - 1) / GBM);
        gemm_tc<<<g, 256>>>(p_h1p, W2, p_h2, N, OUTC, D1);
    }
    att_kernel<<<(N + 7) / 8, 256>>>(p_h2, as2, ad2, p_as2, p_ad2, N, 1);
    agg_kernel<1, false><<<N, OUTC>>>(p_h2, p_as2, p_ad2, p_csr, p_off, b2, out);
}

// round 4
// speedup vs baseline: 1.3166x; 1.0550x over previous
#include <cuda_runtime.h>
#include <cuda_bf16.h>
#include <cstdint>

// Problem constants (fixed shapes per metadata)
#define NMAX   50176
#define EMAX   1048576
#define INF    128
#define HEADS  3
#define HID    64
#define OUTC   64
#define D1     (HEADS*HID)   // 192

// ---------------- static scratch (no runtime allocation) ----------------
__device__ float g_h1 [(size_t)NMAX * D1];
__device__ float g_h1p[(size_t)NMAX * D1];
__device__ float g_h2 [(size_t)NMAX * OUTC];
__device__ float g_as1[(size_t)NMAX * HEADS];
__device__ float g_ad1[(size_t)NMAX * HEADS];
__device__ float g_as2[NMAX];
__device__ float g_ad2[NMAX];
__device__ int   g_cnt [NMAX];
__device__ int   g_fill[NMAX];
__device__ int   g_off [NMAX + 1];
__device__ int   g_csr [EMAX];
__device__ float g_alpha [(size_t)EMAX * HEADS];   // normalized edge weights
__device__ float g_aself [(size_t)NMAX * HEADS];   // normalized self-loop weights

// ---------------- CSR build ----------------
__global__ void zero_kernel(int* a, int* b, int n) {
    int i = blockIdx.x * blockDim.x + threadIdx.x;
    if (i < n) { a[i] = 0; b[i] = 0; }
}

__global__ void hist_kernel(const int* __restrict__ dst, int* __restrict__ cnt, int E) {
    int i = blockIdx.x * blockDim.x + threadIdx.x;
    if (i < E) atomicAdd(&cnt[dst[i]], 1);
}

__global__ void scan_kernel(const int* __restrict__ cnt, int* __restrict__ off, int N) {
    __shared__ int sh[1024];
    int t = threadIdx.x;
    int per = (N + 1023) >> 10;
    int b = t * per;
    int e = min(b + per, N);
    int s = 0;
    for (int i = b; i < e; i++) s += cnt[i];
    sh[t] = s;
    __syncthreads();
    for (int o = 1; o < 1024; o <<= 1) {
        int v = (t >= o) ? sh[t - o] : 0;
        __syncthreads();
        sh[t] += v;
        __syncthreads();
    }
    int run = sh[t] - s;
    for (int i = b; i < e; i++) { off[i] = run; run += cnt[i]; }
    if (t == 1023) off[N] = sh[1023];
}

__global__ void scatter_kernel(const int* __restrict__ src, const int* __restrict__ dst,
                               const int* __restrict__ off, int* __restrict__ fill,
                               int* __restrict__ csr, int E) {
    int i = blockIdx.x * blockDim.x + threadIdx.x;
    if (i < E) {
        int d = dst[i];
        int p = atomicAdd(&fill[d], 1);
        csr[off[d] + p] = src[i];
    }
}

// ---------------- tf32 tensor-core GEMM + fused attention logits ----------------
// C[M,N] = A[M,K]*B[K,N]; BM=128, BN=64 (== one head width), BK=32; 8 warps.
// Epilogue also computes as[row,head] = C_row · ws, ad[row,head] = C_row · wd,
// fully block-local (BN spans exactly one head).
#define GBM 128
#define GBN 64
#define GBK 32
#define AS_STRIDE (GBK + 4)
#define BS_STRIDE 72

__device__ __forceinline__ uint32_t f2tf32(float f) {
    uint32_t r;
    asm volatile("cvt.rna.tf32.f32 %0, %1;\n" : "=r"(r) : "f"(f));
    return r;
}

__device__ __forceinline__ void mma_tf32(float* d, const uint32_t* a, const uint32_t* b) {
    asm volatile(
        "mma.sync.aligned.m16n8k8.row.col.f32.tf32.tf32.f32 "
        "{%0,%1,%2,%3}, {%4,%5,%6,%7}, {%8,%9}, {%0,%1,%2,%3};\n"
        : "+f"(d[0]), "+f"(d[1]), "+f"(d[2]), "+f"(d[3])
        : "r"(a[0]), "r"(a[1]), "r"(a[2]), "r"(a[3]), "r"(b[0]), "r"(b[1]));
}

__global__ void __launch_bounds__(256) gemm_tc_att(const float* __restrict__ A,
                                                   const float* __restrict__ B,
                                                   float* __restrict__ C,
                                                   const float* __restrict__ ws,
                                                   const float* __restrict__ wd,
                                                   float* __restrict__ as_o,
                                                   float* __restrict__ ad_o,
                                                   int M, int N, int K, int H) {
    __shared__ uint32_t As[GBM][AS_STRIDE];   // 18 KB
    __shared__ uint32_t Bs[GBK][BS_STRIDE];   // 9 KB
    __shared__ float s_ws[GBN], s_wd[GBN];
    __shared__ float s_rs[8][32], s_rd[8][32];
    int bm = blockIdx.y * GBM, bn = blockIdx.x * GBN;
    int head = blockIdx.x;
    int tid  = threadIdx.x;
    int lane = tid & 31;
    int warp = tid >> 5;
    int wm = (warp >> 1) * 32;
    int wn = (warp & 1) * 32;

    if (tid < GBN) {
        s_ws[tid] = ws[head * GBN + tid];
        s_wd[tid] = wd[head * GBN + tid];
    }

    int a_r   = tid >> 3;
    int a_kc  = (tid & 7) << 2;
    int b_k   = tid >> 4;
    int b_n   = (tid & 15) << 2;

    float d[2][4][4];
#pragma unroll
    for (int i = 0; i < 2; i++)
#pragma unroll
        for (int j = 0; j < 4; j++)
#pragma unroll
            for (int l = 0; l < 4; l++) d[i][j][l] = 0.f;

    int g = lane >> 2;
    int tg = lane & 3;

    for (int k0 = 0; k0 < K; k0 += GBK) {
#pragma unroll
        for (int i = 0; i < 4; i++) {
            int row = a_r + i * 32;
            int grow = bm + row;
            grow = grow < M ? grow : M - 1;
            float4 v = *(const float4*)(A + (size_t)grow * K + k0 + a_kc);
            uint4 u;
            u.x = f2tf32(v.x); u.y = f2tf32(v.y); u.z = f2tf32(v.z); u.w = f2tf32(v.w);
            *(uint4*)&As[row][a_kc] = u;
        }
#pragma unroll
        for (int i = 0; i < 2; i++) {
            int kk = b_k + i * 16;
            float4 v = *(const float4*)(B + (size_t)(k0 + kk) * N + bn + b_n);
            uint4 u;
            u.x = f2tf32(v.x); u.y = f2tf32(v.y); u.z = f2tf32(v.z); u.w = f2tf32(v.w);
            *(uint4*)&Bs[kk][b_n] = u;
        }
        __syncthreads();
#pragma unroll
        for (int kk = 0; kk < GBK; kk += 8) {
            uint32_t afrag[2][4];
#pragma unroll
            for (int mi = 0; mi < 2; mi++) {
                int r = wm + mi * 16 + g;
                afrag[mi][0] = As[r][kk + tg];
                afrag[mi][1] = As[r + 8][kk + tg];
                afrag[mi][2] = As[r][kk + tg + 4];
                afrag[mi][3] = As[r + 8][kk + tg + 4];
            }
#pragma unroll
            for (int ni = 0; ni < 4; ni++) {
                uint32_t bfrag[2];
                int n = wn + ni * 8 + g;
                bfrag[0] = Bs[kk + tg][n];
                bfrag[1] = Bs[kk + tg + 4][n];
                mma_tf32(d[0][ni], afrag[0], bfrag);
                mma_tf32(d[1][ni], afrag[1], bfrag);
            }
        }
        __syncthreads();
    }

    // ---- C stores ----
#pragma unroll
    for (int mi = 0; mi < 2; mi++) {
#pragma unroll
        for (int ni = 0; ni < 4; ni++) {
            int r0 = bm + wm + mi * 16 + g;
            int c  = bn + wn + ni * 8 + tg * 2;
            if (r0 < M)
                *(float2*)(C + (size_t)r0 * N + c) = make_float2(d[mi][ni][0], d[mi][ni][1]);
            if (r0 + 8 < M)
                *(float2*)(C + (size_t)(r0 + 8) * N + c) = make_float2(d[mi][ni][2], d[mi][ni][3]);
        }
    }

    // ---- fused attention-logit reduction ----
    // per-thread partials for its 4 rows over its 8 cols
#pragma unroll
    for (int mi = 0; mi < 2; mi++) {
        float ps0 = 0.f, pd0 = 0.f, ps1 = 0.f, pd1 = 0.f;
#pragma unroll
        for (int ni = 0; ni < 4; ni++) {
            int c = wn + ni * 8 + tg * 2;   // block-local col
            ps0 = fmaf(d[mi][ni][0], s_ws[c], ps0);
            ps0 = fmaf(d[mi][ni][1], s_ws[c + 1], ps0);
            pd0 = fmaf(d[mi][ni][0], s_wd[c], pd0);
            pd0 = fmaf(d[mi][ni][1], s_wd[c + 1], pd0);
            ps1 = fmaf(d[mi][ni][2], s_ws[c], ps1);
            ps1 = fmaf(d[mi][ni][3], s_ws[c + 1], ps1);
            pd1 = fmaf(d[mi][ni][2], s_wd[c], pd1);
            pd1 = fmaf(d[mi][ni][3], s_wd[c + 1], pd1);
        }
        // reduce over the 4 tg-lanes that share each row
#pragma unroll
        for (int o = 1; o < 4; o <<= 1) {
            ps0 += __shfl_xor_sync(~0u, ps0, o);
            pd0 += __shfl_xor_sync(~0u, pd0, o);
            ps1 += __shfl_xor_sync(~0u, ps1, o);
            pd1 += __shfl_xor_sync(~0u, pd1, o);
        }
        if (tg == 0) {
            s_rs[warp][mi * 16 + g]     = ps0;
            s_rd[warp][mi * 16 + g]     = pd0;
            s_rs[warp][mi * 16 + 8 + g] = ps1;
            s_rd[warp][mi * 16 + 8 + g] = pd1;
        }
    }
    __syncthreads();
    if ((warp & 1) == 0) {
        int rr = lane;
        int row = bm + (warp >> 1) * 32 + rr;
        if (row < M) {
            as_o[(size_t)row * H + head] = s_rs[warp][rr] + s_rs[warp + 1][rr];
            ad_o[(size_t)row * H + head] = s_rd[warp][rr] + s_rd[warp + 1][rr];
        }
    }
}

// ---------------- alpha precompute: warp per node, lanes parallel over edges ----
// Computes normalized softmax weights for all in-edges + the self loop.
template <int H>
__global__ void __launch_bounds__(256) alpha_kernel(const float* __restrict__ as,
                                                    const float* __restrict__ ad,
                                                    const int* __restrict__ csr,
                                                    const int* __restrict__ off,
                                                    float* __restrict__ alpha,
                                                    float* __restrict__ aself,
                                                    int N) {
    constexpr int RREG = 4;
    int i    = (blockIdx.x * blockDim.x + threadIdx.x) >> 5;
    int lane = threadIdx.x & 31;
    if (i >= N) return;

    float ad_i[H], eself[H], m[H];
#pragma unroll
    for (int h = 0; h < H; h++) {
        ad_i[h] = __ldg(&ad[(size_t)i * H + h]);
        float e = __ldg(&as[(size_t)i * H + h]) + ad_i[h];
        eself[h] = e > 0.f ? e : 0.2f * e;
        m[h] = eself[h];
    }

    int b0 = off[i];
    int deg = off[i + 1] - b0;
    int nr = (deg + 31) >> 5;

    float e[RREG][H];
#pragma unroll
    for (int r = 0; r < RREG; r++) {
        int j = r * 32 + lane;
        if (r * 32 < deg && j < deg) {
            int s = __ldg(&csr[b0 + j]);
#pragma unroll
            for (int h = 0; h < H; h++) {
                float v = __ldg(&as[(size_t)s * H + h]) + ad_i[h];
                e[r][h] = v > 0.f ? v : 0.2f * v;
                m[h] = fmaxf(m[h], e[r][h]);
            }
        } else {
#pragma unroll
            for (int h = 0; h < H; h++) e[r][h] = -1e30f;
        }
    }
    // rare overflow rounds (deg > 128)
    for (int r = RREG; r < nr; r++) {
        int j = r * 32 + lane;
        if (j < deg) {
            int s = __ldg(&csr[b0 + j]);
#pragma unroll
            for (int h = 0; h < H; h++) {
                float v = __ldg(&as[(size_t)s * H + h]) + ad_i[h];
                v = v > 0.f ? v : 0.2f * v;
                m[h] = fmaxf(m[h], v);
            }
        }
    }
    // warp max
#pragma unroll
    for (int h = 0; h < H; h++)
#pragma unroll
        for (int o = 16; o; o >>= 1) m[h] = fmaxf(m[h], __shfl_xor_sync(~0u, m[h], o));

    // sums
    float den[H];
#pragma unroll
    for (int h = 0; h < H; h++) den[h] = 0.f;
#pragma unroll
    for (int r = 0; r < RREG; r++) {
        int j = r * 32 + lane;
        if (r * 32 < deg && j < deg)
#pragma unroll
            for (int h = 0; h < H; h++) den[h] += __expf(e[r][h] - m[h]);
    }
    for (int r = RREG; r < nr; r++) {
        int j = r * 32 + lane;
        if (j < deg) {
            int s = __ldg(&csr[b0 + j]);
#pragma unroll
            for (int h = 0; h < H; h++) {
                float v = __ldg(&as[(size_t)s * H + h]) + ad_i[h];
                v = v > 0.f ? v : 0.2f * v;
                den[h] += __expf(v - m[h]);
            }
        }
    }
    float inv[H];
#pragma unroll
    for (int h = 0; h < H; h++) {
#pragma unroll
        for (int o = 16; o; o >>= 1) den[h] += __shfl_xor_sync(~0u, den[h], o);
        den[h] += __expf(eself[h] - m[h]);
        inv[h] = 1.0f / (den[h] + 1e-16f);
    }

    // writes
#pragma unroll
    for (int r = 0; r < RREG; r++) {
        int j = r * 32 + lane;
        if (r * 32 < deg && j < deg)
#pragma unroll
            for (int h = 0; h < H; h++)
                alpha[(size_t)(b0 + j) * H + h] = __expf(e[r][h] - m[h]) * inv[h];
    }
    for (int r = RREG; r < nr; r++) {
        int j = r * 32 + lane;
        if (j < deg) {
            int s = __ldg(&csr[b0 + j]);
#pragma unroll
            for (int h = 0; h < H; h++) {
                float v = __ldg(&as[(size_t)s * H + h]) + ad_i[h];
                v = v > 0.f ? v : 0.2f * v;
                alpha[(size_t)(b0 + j) * H + h] = __expf(v - m[h]) * inv[h];
            }
        }
    }
    if (lane == 0)
#pragma unroll
        for (int h = 0; h < H; h++)
            aself[(size_t)i * H + h] = __expf(eself[h] - m[h]) * inv[h];
}

// ---------------- weighted gather-aggregate (pure, no softmax, no syncs) ------
// One block per node; blockDim = H*64; thread owns (head=tid>>6, ch=tid&63).
template <int H, bool ACT>
__global__ void __launch_bounds__(H * 64) agg_kernel(const float* __restrict__ h,
                                                     const float* __restrict__ alpha,
                                                     const float* __restrict__ aself,
                                                     const int* __restrict__ csr,
                                                     const int* __restrict__ off,
                                                     const float* __restrict__ bias,
                                                     float* __restrict__ out) {
    constexpr int D = H * 64;
    int i    = blockIdx.x;
    int tid  = threadIdx.x;
    int head = tid >> 6;

    float acc = __ldg(&aself[(size_t)i * H + head]) * __ldg(&h[(size_t)i * D + tid]);

    int b0 = off[i], b1 = off[i + 1];
    int j = b0;
    for (; j + 8 <= b1; j += 8) {
        int   s[8];
        float w[8], v[8];
#pragma unroll
        for (int k = 0; k < 8; k++) s[k] = __ldg(&csr[j + k]);
#pragma unroll
        for (int k = 0; k < 8; k++) w[k] = __ldg(&alpha[(size_t)(j + k) * H + head]);
#pragma unroll
        for (int k = 0; k < 8; k++) v[k] = __ldg(&h[(size_t)s[k] * D + tid]);
#pragma unroll
        for (int k = 0; k < 8; k++) acc = fmaf(w[k], v[k], acc);
    }
    for (; j < b1; j++) {
        int s = __ldg(&csr[j]);
        float w = __ldg(&alpha[(size_t)j * H + head]);
        acc = fmaf(w, __ldg(&h[(size_t)s * D + tid]), acc);
    }

    float r = acc + bias[tid];
    if (ACT) r = r > 0.f ? r : expm1f(r);
    out[(size_t)i * D + tid] = r;
}

// ---------------- launch ----------------
extern "C" void kernel_launch(void* const* d_in, const int* in_sizes, int n_in,
                              void* d_out, int out_size) {
    const float* x   = (const float*)d_in[0];
    const int*   ei  = (const int*)  d_in[1];
    const float* W1  = (const float*)d_in[2];
    const float* as1 = (const float*)d_in[3];
    const float* ad1 = (const float*)d_in[4];
    const float* b1  = (const float*)d_in[5];
    const float* W2  = (const float*)d_in[6];
    const float* as2 = (const float*)d_in[7];
    const float* ad2 = (const float*)d_in[8];
    const float* b2  = (const float*)d_in[9];
    float* out = (float*)d_out;

    int N = in_sizes[0] / INF;
    int E = in_sizes[1] / 2;
    const int* esrc = ei;
    const int* edst = ei + E;

    float *p_h1, *p_h1p, *p_h2, *p_as1, *p_ad1, *p_as2, *p_ad2, *p_alpha, *p_aself;
    int *p_cnt, *p_fill, *p_off, *p_csr;
    cudaGetSymbolAddress((void**)&p_h1,  g_h1);
    cudaGetSymbolAddress((void**)&p_h1p, g_h1p);
    cudaGetSymbolAddress((void**)&p_h2,  g_h2);
    cudaGetSymbolAddress((void**)&p_as1, g_as1);
    cudaGetSymbolAddress((void**)&p_ad1, g_ad1);
    cudaGetSymbolAddress((void**)&p_as2, g_as2);
    cudaGetSymbolAddress((void**)&p_ad2, g_ad2);
    cudaGetSymbolAddress((void**)&p_cnt,  g_cnt);
    cudaGetSymbolAddress((void**)&p_fill, g_fill);
    cudaGetSymbolAddress((void**)&p_off,  g_off);
    cudaGetSymbolAddress((void**)&p_csr,  g_csr);
    cudaGetSymbolAddress((void**)&p_alpha, g_alpha);
    cudaGetSymbolAddress((void**)&p_aself, g_aself);

    static cudaStream_t s_side = nullptr;
    static cudaEvent_t  ev_fork = nullptr, ev_join = nullptr;
    if (s_side == nullptr) {
        cudaStreamCreateWithFlags(&s_side, cudaStreamNonBlocking);
        cudaEventCreateWithFlags(&ev_fork, cudaEventDisableTiming);
        cudaEventCreateWithFlags(&ev_join, cudaEventDisableTiming);
    }
    bool forked = (s_side != nullptr && ev_fork != nullptr && ev_join != nullptr);
    cudaStream_t sc = forked ? s_side : (cudaStream_t)0;

    if (forked) {
        cudaEventRecord(ev_fork, 0);
        cudaStreamWaitEvent(s_side, ev_fork, 0);
    }
    // CSR build (by destination) — overlapped with layer-1 GEMM
    zero_kernel<<<(N + 255) / 256, 256, 0, sc>>>(p_cnt, p_fill, N);
    hist_kernel<<<(E + 255) / 256, 256, 0, sc>>>(edst, p_cnt, E);
    scan_kernel<<<1, 1024, 0, sc>>>(p_cnt, p_off, N);
    scatter_kernel<<<(E + 255) / 256, 256, 0, sc>>>(esrc, edst, p_off, p_fill, p_csr, E);
    if (forked) cudaEventRecord(ev_join, s_side);

    // Layer 1: GEMM with fused attention logits
    {
        dim3 g(D1 / GBN, (N + GBM - 1) / GBM);
        gemm_tc_att<<<g, 256>>>(x, W1, p_h1, as1, ad1, p_as1, p_ad1, N, D1, INF, HEADS);
    }
    if (forked) cudaStreamWaitEvent(0, ev_join, 0);
    alpha_kernel<HEADS><<<(N + 7) / 8, 256>>>(p_as1, p_ad1, p_csr, p_off, p_alpha, p_aself, N);
    agg_kernel<HEADS, true><<<N, D1>>>(p_h1, p_alpha, p_aself, p_csr, p_off, b1, p_h1p);

    // Layer 2
    {
        dim3 g(OUTC / GBN, (N + GBM - 1) / GBM);
        gemm_tc_att<<<g, 256>>>(p_h1p, W2, p_h2, as2, ad2, p_as2, p_ad2, N, OUTC, D1, 1);
    }
    alpha_kernel<1><<<(N + 7) / 8, 256>>>(p_as2, p_ad2, p_csr, p_off, p_alpha, p_aself, N);
    agg_kernel<1, false><<<N, OUTC>>>(p_h2, p_alpha, p_aself, p_csr, p_off, b2, out);
}

// round 5
// speedup vs baseline: 1.5121x; 1.1485x over previous
#include <cuda_runtime.h>
#include <cuda_bf16.h>
#include <cstdint>

// Problem constants (fixed shapes per metadata)
#define NMAX   50176
#define EMAX   1048576
#define INF    128
#define HEADS  3
#define HID    64
#define OUTC   64
#define D1     (HEADS*HID)   // 192

// ---------------- static scratch (no runtime allocation) ----------------
__device__ float g_h1 [(size_t)NMAX * D1];
__device__ float g_h1p[(size_t)NMAX * D1];
__device__ float g_h2 [(size_t)NMAX * OUTC];
__device__ float g_as1[(size_t)NMAX * HEADS];
__device__ float g_ad1[(size_t)NMAX * HEADS];
__device__ float g_as2[NMAX];
__device__ float g_ad2[NMAX];
__device__ int   g_cnt [NMAX];
__device__ int   g_fill[NMAX];
__device__ int   g_off [NMAX + 1];
__device__ int   g_csr [EMAX];

// ---------------- CSR build ----------------
__global__ void zero_kernel(int* a, int* b, int n) {
    int i = blockIdx.x * blockDim.x + threadIdx.x;
    if (i < n) { a[i] = 0; b[i] = 0; }
}

__global__ void hist_kernel(const int* __restrict__ dst, int* __restrict__ cnt, int E) {
    int i = blockIdx.x * blockDim.x + threadIdx.x;
    if (i < E) atomicAdd(&cnt[dst[i]], 1);
}

__global__ void scan_kernel(const int* __restrict__ cnt, int* __restrict__ off, int N) {
    __shared__ int sh[1024];
    int t = threadIdx.x;
    int per = (N + 1023) >> 10;
    int b = t * per;
    int e = min(b + per, N);
    int s = 0;
    for (int i = b; i < e; i++) s += cnt[i];
    sh[t] = s;
    __syncthreads();
    for (int o = 1; o < 1024; o <<= 1) {
        int v = (t >= o) ? sh[t - o] : 0;
        __syncthreads();
        sh[t] += v;
        __syncthreads();
    }
    int run = sh[t] - s;
    for (int i = b; i < e; i++) { off[i] = run; run += cnt[i]; }
    if (t == 1023) off[N] = sh[1023];
}

__global__ void scatter_kernel(const int* __restrict__ src, const int* __restrict__ dst,
                               const int* __restrict__ off, int* __restrict__ fill,
                               int* __restrict__ csr, int E) {
    int i = blockIdx.x * blockDim.x + threadIdx.x;
    if (i < E) {
        int d = dst[i];
        int p = atomicAdd(&fill[d], 1);
        csr[off[d] + p] = src[i];
    }
}

// ---------------- tf32 tensor-core GEMM + fused attention logits ----------------
#define GBM 128
#define GBN 64
#define GBK 32
#define AS_STRIDE (GBK + 4)
#define BS_STRIDE 72

__device__ __forceinline__ uint32_t f2tf32(float f) {
    uint32_t r;
    asm volatile("cvt.rna.tf32.f32 %0, %1;\n" : "=r"(r) : "f"(f));
    return r;
}

__device__ __forceinline__ void mma_tf32(float* d, const uint32_t* a, const uint32_t* b) {
    asm volatile(
        "mma.sync.aligned.m16n8k8.row.col.f32.tf32.tf32.f32 "
        "{%0,%1,%2,%3}, {%4,%5,%6,%7}, {%8,%9}, {%0,%1,%2,%3};\n"
        : "+f"(d[0]), "+f"(d[1]), "+f"(d[2]), "+f"(d[3])
        : "r"(a[0]), "r"(a[1]), "r"(a[2]), "r"(a[3]), "r"(b[0]), "r"(b[1]));
}

__global__ void __launch_bounds__(256) gemm_tc_att(const float* __restrict__ A,
                                                   const float* __restrict__ B,
                                                   float* __restrict__ C,
                                                   const float* __restrict__ ws,
                                                   const float* __restrict__ wd,
                                                   float* __restrict__ as_o,
                                                   float* __restrict__ ad_o,
                                                   int M, int N, int K, int H) {
    __shared__ uint32_t As[GBM][AS_STRIDE];   // 18 KB
    __shared__ uint32_t Bs[GBK][BS_STRIDE];   // 9 KB
    __shared__ float s_ws[GBN], s_wd[GBN];
    __shared__ float s_rs[8][32], s_rd[8][32];
    int bm = blockIdx.y * GBM, bn = blockIdx.x * GBN;
    int head = blockIdx.x;
    int tid  = threadIdx.x;
    int lane = tid & 31;
    int warp = tid >> 5;
    int wm = (warp >> 1) * 32;
    int wn = (warp & 1) * 32;

    if (tid < GBN) {
        s_ws[tid] = ws[head * GBN + tid];
        s_wd[tid] = wd[head * GBN + tid];
    }

    int a_r   = tid >> 3;
    int a_kc  = (tid & 7) << 2;
    int b_k   = tid >> 4;
    int b_n   = (tid & 15) << 2;

    float d[2][4][4];
#pragma unroll
    for (int i = 0; i < 2; i++)
#pragma unroll
        for (int j = 0; j < 4; j++)
#pragma unroll
            for (int l = 0; l < 4; l++) d[i][j][l] = 0.f;

    int g = lane >> 2;
    int tg = lane & 3;

    for (int k0 = 0; k0 < K; k0 += GBK) {
#pragma unroll
        for (int i = 0; i < 4; i++) {
            int row = a_r + i * 32;
            int grow = bm + row;
            grow = grow < M ? grow : M - 1;
            float4 v = *(const float4*)(A + (size_t)grow * K + k0 + a_kc);
            uint4 u;
            u.x = f2tf32(v.x); u.y = f2tf32(v.y); u.z = f2tf32(v.z); u.w = f2tf32(v.w);
            *(uint4*)&As[row][a_kc] = u;
        }
#pragma unroll
        for (int i = 0; i < 2; i++) {
            int kk = b_k + i * 16;
            float4 v = *(const float4*)(B + (size_t)(k0 + kk) * N + bn + b_n);
            uint4 u;
            u.x = f2tf32(v.x); u.y = f2tf32(v.y); u.z = f2tf32(v.z); u.w = f2tf32(v.w);
            *(uint4*)&Bs[kk][b_n] = u;
        }
        __syncthreads();
#pragma unroll
        for (int kk = 0; kk < GBK; kk += 8) {
            uint32_t afrag[2][4];
#pragma unroll
            for (int mi = 0; mi < 2; mi++) {
                int r = wm + mi * 16 + g;
                afrag[mi][0] = As[r][kk + tg];
                afrag[mi][1] = As[r + 8][kk + tg];
                afrag[mi][2] = As[r][kk + tg + 4];
                afrag[mi][3] = As[r + 8][kk + tg + 4];
            }
#pragma unroll
            for (int ni = 0; ni < 4; ni++) {
                uint32_t bfrag[2];
                int n = wn + ni * 8 + g;
                bfrag[0] = Bs[kk + tg][n];
                bfrag[1] = Bs[kk + tg + 4][n];
                mma_tf32(d[0][ni], afrag[0], bfrag);
                mma_tf32(d[1][ni], afrag[1], bfrag);
            }
        }
        __syncthreads();
    }

    // ---- C stores ----
#pragma unroll
    for (int mi = 0; mi < 2; mi++) {
#pragma unroll
        for (int ni = 0; ni < 4; ni++) {
            int r0 = bm + wm + mi * 16 + g;
            int c  = bn + wn + ni * 8 + tg * 2;
            if (r0 < M)
                *(float2*)(C + (size_t)r0 * N + c) = make_float2(d[mi][ni][0], d[mi][ni][1]);
            if (r0 + 8 < M)
                *(float2*)(C + (size_t)(r0 + 8) * N + c) = make_float2(d[mi][ni][2], d[mi][ni][3]);
        }
    }

    // ---- fused attention-logit reduction ----
#pragma unroll
    for (int mi = 0; mi < 2; mi++) {
        float ps0 = 0.f, pd0 = 0.f, ps1 = 0.f, pd1 = 0.f;
#pragma unroll
        for (int ni = 0; ni < 4; ni++) {
            int c = wn + ni * 8 + tg * 2;
            ps0 = fmaf(d[mi][ni][0], s_ws[c], ps0);
            ps0 = fmaf(d[mi][ni][1], s_ws[c + 1], ps0);
            pd0 = fmaf(d[mi][ni][0], s_wd[c], pd0);
            pd0 = fmaf(d[mi][ni][1], s_wd[c + 1], pd0);
            ps1 = fmaf(d[mi][ni][2], s_ws[c], ps1);
            ps1 = fmaf(d[mi][ni][3], s_ws[c + 1], ps1);
            pd1 = fmaf(d[mi][ni][2], s_wd[c], pd1);
            pd1 = fmaf(d[mi][ni][3], s_wd[c + 1], pd1);
        }
#pragma unroll
        for (int o = 1; o < 4; o <<= 1) {
            ps0 += __shfl_xor_sync(~0u, ps0, o);
            pd0 += __shfl_xor_sync(~0u, pd0, o);
            ps1 += __shfl_xor_sync(~0u, ps1, o);
            pd1 += __shfl_xor_sync(~0u, pd1, o);
        }
        if (tg == 0) {
            s_rs[warp][mi * 16 + g]     = ps0;
            s_rd[warp][mi * 16 + g]     = pd0;
            s_rs[warp][mi * 16 + 8 + g] = ps1;
            s_rd[warp][mi * 16 + 8 + g] = pd1;
        }
    }
    __syncthreads();
    if ((warp & 1) == 0) {
        int rr = lane;
        int row = bm + (warp >> 1) * 32 + rr;
        if (row < M) {
            as_o[(size_t)row * H + head] = s_rs[warp][rr] + s_rs[warp + 1][rr];
            ad_o[(size_t)row * H + head] = s_rd[warp][rr] + s_rd[warp + 1][rr];
        }
    }
}

// ---------------- fused softmax + weighted gather, warp per (node, head) -----
// lane owns 2 channels (float2). deg<=64 fast path keeps csr+logits in regs;
// generic recompute path beyond. No shared memory, no block syncs.
template <int H, bool ACT>
__global__ void __launch_bounds__(256) agg_fused(const float* __restrict__ h,
                                                 const float* __restrict__ as,
                                                 const float* __restrict__ ad,
                                                 const int* __restrict__ csr,
                                                 const int* __restrict__ off,
                                                 const float* __restrict__ bias,
                                                 float* __restrict__ out, int N) {
    constexpr int D = H * 64;
    constexpr int RREG = 2;   // 64 edges register-resident
    int gw = (blockIdx.x * 256 + threadIdx.x) >> 5;
    if (gw >= N * H) return;
    int i    = gw / H;
    int head = gw - i * H;
    int lane = threadIdx.x & 31;

    int b0  = off[i];
    int deg = off[i + 1] - b0;
    int nr  = (deg + 31) >> 5;

    float ad_i = __ldg(&ad[(size_t)i * H + head]);
    float es   = __ldg(&as[(size_t)i * H + head]) + ad_i;
    es = es > 0.f ? es : 0.2f * es;
    float m = es;

    int   c[RREG];
    float e[RREG];
#pragma unroll
    for (int r = 0; r < RREG; r++) {
        int j = r * 32 + lane;
        c[r] = 0; e[r] = -1e30f;
        if (r * 32 < deg && j < deg) {
            c[r] = __ldg(&csr[b0 + j]);
            float v = __ldg(&as[(size_t)c[r] * H + head]) + ad_i;
            e[r] = v > 0.f ? v : 0.2f * v;
            m = fmaxf(m, e[r]);
        }
    }
    for (int r = RREG; r < nr; r++) {              // rare: deg > 64
        int j = r * 32 + lane;
        if (j < deg) {
            int s = __ldg(&csr[b0 + j]);
            float v = __ldg(&as[(size_t)s * H + head]) + ad_i;
            v = v > 0.f ? v : 0.2f * v;
            m = fmaxf(m, v);
        }
    }
#pragma unroll
    for (int o = 16; o; o >>= 1) m = fmaxf(m, __shfl_xor_sync(~0u, m, o));

    float den = 0.f;
#pragma unroll
    for (int r = 0; r < RREG; r++) {
        float w = (e[r] > -1e29f) ? __expf(e[r] - m) : 0.f;
        e[r] = w;                      // e[] now holds unnormalized weights
        den += w;
    }
    for (int r = RREG; r < nr; r++) {
        int j = r * 32 + lane;
        if (j < deg) {
            int s = __ldg(&csr[b0 + j]);
            float v = __ldg(&as[(size_t)s * H + head]) + ad_i;
            v = v > 0.f ? v : 0.2f * v;
            den += __expf(v - m);
        }
    }
#pragma unroll
    for (int o = 16; o; o >>= 1) den += __shfl_xor_sync(~0u, den, o);
    float wself = __expf(es - m);
    den += wself;
    float inv = 1.0f / (den + 1e-16f);

    int chbase = head * 64 + 2 * lane;
    float2 acc;
    {
        float2 v = *(const float2*)(h + (size_t)i * D + chbase);
        float w = wself * inv;
        acc.x = w * v.x; acc.y = w * v.y;
    }

#pragma unroll
    for (int r = 0; r < RREG; r++) {
        if (r * 32 >= deg) break;
        int cnt = min(32, deg - r * 32);
        float wn = e[r] * inv;
        int k = 0;
        for (; k + 8 <= cnt; k += 8) {
            int s[8]; float2 v[8]; float w[8];
#pragma unroll
            for (int t = 0; t < 8; t++) s[t] = __shfl_sync(~0u, c[r], k + t);
#pragma unroll
            for (int t = 0; t < 8; t++) v[t] = *(const float2*)(h + (size_t)s[t] * D + chbase);
#pragma unroll
            for (int t = 0; t < 8; t++) w[t] = __shfl_sync(~0u, wn, k + t);
#pragma unroll
            for (int t = 0; t < 8; t++) {
                acc.x = fmaf(w[t], v[t].x, acc.x);
                acc.y = fmaf(w[t], v[t].y, acc.y);
            }
        }
        for (; k < cnt; k++) {
            int s   = __shfl_sync(~0u, c[r], k);
            float w = __shfl_sync(~0u, wn, k);
            float2 v = *(const float2*)(h + (size_t)s * D + chbase);
            acc.x = fmaf(w, v.x, acc.x);
            acc.y = fmaf(w, v.y, acc.y);
        }
    }
    for (int r = RREG; r < nr; r++) {              // rare: deg > 64
        int j = r * 32 + lane;
        int s_ = 0; float wn = 0.f;
        if (j < deg) {
            s_ = __ldg(&csr[b0 + j]);
            float v = __ldg(&as[(size_t)s_ * H + head]) + ad_i;
            v = v > 0.f ? v : 0.2f * v;
            wn = __expf(v - m) * inv;
        }
        int cnt = min(32, deg - r * 32);
        for (int k = 0; k < cnt; k++) {
            int s   = __shfl_sync(~0u, s_, k);
            float w = __shfl_sync(~0u, wn, k);
            float2 v = *(const float2*)(h + (size_t)s * D + chbase);
            acc.x = fmaf(w, v.x, acc.x);
            acc.y = fmaf(w, v.y, acc.y);
        }
    }

    float2 b = *(const float2*)(bias + chbase);
    float rx = acc.x + b.x, ry = acc.y + b.y;
    if (ACT) {
        rx = rx > 0.f ? rx : expm1f(rx);
        ry = ry > 0.f ? ry : expm1f(ry);
    }
    *(float2*)(out + (size_t)i * D + chbase) = make_float2(rx, ry);
}

// ---------------- launch ----------------
extern "C" void kernel_launch(void* const* d_in, const int* in_sizes, int n_in,
                              void* d_out, int out_size) {
    const float* x   = (const float*)d_in[0];
    const int*   ei  = (const int*)  d_in[1];
    const float* W1  = (const float*)d_in[2];
    const float* as1 = (const float*)d_in[3];
    const float* ad1 = (const float*)d_in[4];
    const float* b1  = (const float*)d_in[5];
    const float* W2  = (const float*)d_in[6];
    const float* as2 = (const float*)d_in[7];
    const float* ad2 = (const float*)d_in[8];
    const float* b2  = (const float*)d_in[9];
    float* out = (float*)d_out;

    int N = in_sizes[0] / INF;
    int E = in_sizes[1] / 2;
    const int* esrc = ei;
    const int* edst = ei + E;

    float *p_h1, *p_h1p, *p_h2, *p_as1, *p_ad1, *p_as2, *p_ad2;
    int *p_cnt, *p_fill, *p_off, *p_csr;
    cudaGetSymbolAddress((void**)&p_h1,  g_h1);
    cudaGetSymbolAddress((void**)&p_h1p, g_h1p);
    cudaGetSymbolAddress((void**)&p_h2,  g_h2);
    cudaGetSymbolAddress((void**)&p_as1, g_as1);
    cudaGetSymbolAddress((void**)&p_ad1, g_ad1);
    cudaGetSymbolAddress((void**)&p_as2, g_as2);
    cudaGetSymbolAddress((void**)&p_ad2, g_ad2);
    cudaGetSymbolAddress((void**)&p_cnt,  g_cnt);
    cudaGetSymbolAddress((void**)&p_fill, g_fill);
    cudaGetSymbolAddress((void**)&p_off,  g_off);
    cudaGetSymbolAddress((void**)&p_csr,  g_csr);

    static cudaStream_t s_side = nullptr;
    static cudaEvent_t  ev_fork = nullptr, ev_join = nullptr;
    if (s_side == nullptr) {
        cudaStreamCreateWithFlags(&s_side, cudaStreamNonBlocking);
        cudaEventCreateWithFlags(&ev_fork, cudaEventDisableTiming);
        cudaEventCreateWithFlags(&ev_join, cudaEventDisableTiming);
    }
    bool forked = (s_side != nullptr && ev_fork != nullptr && ev_join != nullptr);
    cudaStream_t sc = forked ? s_side : (cudaStream_t)0;

    if (forked) {
        cudaEventRecord(ev_fork, 0);
        cudaStreamWaitEvent(s_side, ev_fork, 0);
    }
    // CSR build (by destination) — overlapped with layer-1 GEMM
    zero_kernel<<<(N + 255) / 256, 256, 0, sc>>>(p_cnt, p_fill, N);
    hist_kernel<<<(E + 255) / 256, 256, 0, sc>>>(edst, p_cnt, E);
    scan_kernel<<<1, 1024, 0, sc>>>(p_cnt, p_off, N);
    scatter_kernel<<<(E + 255) / 256, 256, 0, sc>>>(esrc, edst, p_off, p_fill, p_csr, E);
    if (forked) cudaEventRecord(ev_join, s_side);

    // Layer 1: GEMM with fused attention logits
    {
        dim3 g(D1 / GBN, (N + GBM - 1) / GBM);
        gemm_tc_att<<<g, 256>>>(x, W1, p_h1, as1, ad1, p_as1, p_ad1, N, D1, INF, HEADS);
    }
    if (forked) cudaStreamWaitEvent(0, ev_join, 0);
    agg_fused<HEADS, true><<<(N * HEADS + 7) / 8, 256>>>(p_h1, p_as1, p_ad1, p_csr, p_off, b1, p_h1p, N);

    // Layer 2
    {
        dim3 g(OUTC / GBN, (N + GBM - 1) / GBM);
        gemm_tc_att<<<g, 256>>>(p_h1p, W2, p_h2, as2, ad2, p_as2, p_ad2, N, OUTC, D1, 1);
    }
    agg_fused<1, false><<<(N + 7) / 8, 256>>>(p_h2, p_as2, p_ad2, p_csr, p_off, b2, out, N);
}